// round 16
// baseline (speedup 1.0000x reference)
#include <cuda_runtime.h>
#include <cuda_fp16.h>
#include <cstdint>

#define BATCH 2048
#define RPOS  60
#define KW    13
#define CIN   64
#define CMID  64
#define COUT  128
#define EPSV  1e-5f

__device__ __align__(128) __half g_W1p[KW * CMID * CIN];
__device__ __align__(128) __half g_W2p[KW * COUT * CMID];
__device__ __align__(128) __half g_W3p[KW * COUT * CMID];

__device__ __forceinline__ uint32_t smem_u32(const void* p) {
    uint32_t a;
    asm("{ .reg .u64 t; cvta.to.shared.u64 t, %1; cvt.u32.u64 %0, t; }" : "=r"(a) : "l"(p));
    return a;
}

#define CP_ASYNC16(dst, src) \
    asm volatile("cp.async.cg.shared.global [%0], [%1], 16;" :: "r"(dst), "l"(src) : "memory")
#define CP_COMMIT()  asm volatile("cp.async.commit_group;" ::: "memory")
#define CP_WAIT(n)   asm volatile("cp.async.wait_group %0;" :: "n"(n) : "memory")

#define LDMX4(r0, r1, r2, r3, addr) \
    asm volatile("ldmatrix.sync.aligned.m8n8.x4.shared.b16 {%0,%1,%2,%3}, [%4];" \
        : "=r"(r0), "=r"(r1), "=r"(r2), "=r"(r3) : "r"(addr))

__device__ __forceinline__ void mma_f16(float* d, const uint32_t* a, const uint32_t* b) {
    asm volatile("mma.sync.aligned.m16n8k16.row.col.f32.f16.f16.f32 "
        "{%0,%1,%2,%3},{%4,%5,%6,%7},{%8,%9},{%0,%1,%2,%3};"
        : "+f"(d[0]), "+f"(d[1]), "+f"(d[2]), "+f"(d[3])
        : "r"(a[0]), "r"(a[1]), "r"(a[2]), "r"(a[3]), "r"(b[0]), "r"(b[1]));
}

__global__ void packW_kernel(const float* __restrict__ W1, const float* __restrict__ W2,
                             const float* __restrict__ W3)
{
    int idx = blockIdx.x * 256 + threadIdx.x;
    const int n1 = KW * CMID * CIN, n2 = KW * COUT * CMID;
    const float* W; __half* dst; int O, nloc;
    if (idx < n1)              { W = W1; dst = g_W1p; O = CMID; nloc = idx;           }
    else if (idx < n1 + n2)    { W = W2; dst = g_W2p; O = COUT; nloc = idx - n1;      }
    else if (idx < n1 + 2*n2)  { W = W3; dst = g_W3p; O = COUT; nloc = idx - n1 - n2; }
    else return;
    int k = nloc / (O * 64), rem = nloc % (O * 64);
    int o = rem / 64, c = rem % 64;
    float v = W[o * (64 * KW) + c * KW + k];
    int sw = ((c >> 3) ^ (o & 7)) * 8 + (c & 7);
    dst[(size_t)(k * O + o) * 64 + sw] = __float2half_rn(v);
}

// smem (per CTA, ~99.4 KB -> 2 CTAs/SM at 128 regs):
//   FY12: y1 during conv1, overwritten by y2 at phase switch (15360)
//   FY3 : y3 (15360)
//   FWO : W QUAD buffer 4x16384 (x staging overlaps in prologue)
#define FY12  0u
#define FY3   15360u
#define FWO   30720u
#define FNEI  96256u
#define FBIAS (FNEI + 3200u)
#define FTOT  (FBIAS + 2304u)

__global__ __launch_bounds__(256, 2)
void fused_kernel(const float* __restrict__ x, const int* __restrict__ nei,
                  const float* __restrict__ g1, const float* __restrict__ b1,
                  const float* __restrict__ m1, const float* __restrict__ v1,
                  const float* __restrict__ c1,
                  const float* __restrict__ g2, const float* __restrict__ b2,
                  const float* __restrict__ m2, const float* __restrict__ v2,
                  const float* __restrict__ g3, const float* __restrict__ b3,
                  const float* __restrict__ m3, const float* __restrict__ v3,
                  const float* __restrict__ cc2, const float* __restrict__ cc3,
                  float* __restrict__ out)
{
    extern __shared__ __align__(1024) char smb[];
    uint32_t sbase = smem_u32(smb);

    int t = threadIdx.x, wid = t >> 5, l = t & 31;
    int*   snei = (int*)(smb + FNEI);
    float* sb   = (float*)(smb + FBIAS);

    for (int i = t; i < RPOS * KW; i += 256) snei[i] = nei[i];
    if (t < 64) {
        sb[t] = c1[t];
        float iv = g2[t] * rsqrtf(v2[t] + EPSV);
        sb[64 + t] = iv; sb[128 + t] = b2[t] - m2[t] * iv;
        float i1 = g1[t] * rsqrtf(v1[t] + EPSV);
        sb[192 + t] = i1; sb[256 + t] = b1[t] - m1[t] * i1;
        float i3 = g3[t] * rsqrtf(v3[t] + EPSV);
        sb[320 + t] = i3; sb[384 + t] = b3[t] - m3[t] * i3;
    }
    if (t < 128) sb[448 + t] = cc2[t] + cc3[t];

    int b0 = blockIdx.x * 2;

    // prologue A: stage x into W-buffer region (floats, [bb][c][j] stride 61)
    float* xs = (float*)(smb + FWO);
    const float* xsrc = x + (size_t)b0 * (CIN * RPOS);
    for (int i = t; i < 2 * CIN * RPOS; i += 256) {
        int bb = i / 3840, rem = i - bb * 3840;
        int c = rem / 60, j = rem - c * 60;
        xs[(bb * 64 + c) * 61 + j] = xsrc[i];
    }
    __syncthreads();

    // prologue B: y1 (-> FY12), y3 fp16 tiles; per-row swizzle key = r&7
    for (int i = t; i < 2 * RPOS * 32; i += 256) {
        int bb = i / 1920, rem = i - bb * 1920;
        int r = rem >> 5, cp = rem & 31, c = cp * 2;
        const float* xc = xs + (bb * 64 + c) * 61 + r;
        float xa = xc[0], xb2 = xc[61];
        float a1  = fmaxf(fmaf(xa,  sb[192 + c], sb[256 + c]), 0.0f);
        float b1v = fmaxf(fmaf(xb2, sb[193 + c], sb[257 + c]), 0.0f);
        float a3  = fmaxf(fmaf(xa,  sb[320 + c], sb[384 + c]), 0.0f);
        float b3v = fmaxf(fmaf(xb2, sb[321 + c], sb[385 + c]), 0.0f);
        uint32_t off = (uint32_t)((bb * 60 + r) * 128
                     + (((cp >> 2) ^ (r & 7)) << 4) + ((cp & 3) << 2));
        *(__half2*)(smb + FY12 + off) = __floats2half2_rn(a1, b1v);
        *(__half2*)(smb + FY3  + off) = __floats2half2_rn(a3, b3v);
    }
    __syncthreads();   // xs consumed; W prefetch may overwrite

    int wrow1 = t >> 2, wq1 = t & 3;   // conv1 W: 64 rows x 32B
    int wrow2 = t >> 1, wh2 = t & 1;   // conv2 W: 128 rows x 64B

    // prefetch W stages 0 and 1 into slots 0,1 as ONE group
    {
        const char* ws = (const char*)g_W1p + ((size_t)wrow1 << 7) + (size_t)(wq1 * 32);
        uint32_t dst = sbase + FWO + (uint32_t)(wrow1 * 128 + wq1 * 32);
        CP_ASYNC16(dst, ws); CP_ASYNC16(dst + 16, ws + 16);
        ws = (const char*)g_W1p + ((size_t)(CMID + wrow1) << 7) + (size_t)(wq1 * 32);
        dst = sbase + FWO + 16384u + (uint32_t)(wrow1 * 128 + wq1 * 32);
        CP_ASYNC16(dst, ws); CP_ASYNC16(dst + 16, ws + 16);
        CP_COMMIT();
    }

    int m0 = (wid & 3) * 32;
    int n1_0 = (wid >> 2) * 32;
    int n2_0 = (wid >> 2) * 64;
    int lrA = l & 15, lgA = l >> 4;
    int lrB = (l & 7) + ((l >> 4) << 3), lgB = (l >> 3) & 1;
    // XOR-folded constants: addr = C ^ (ks<<5); bases are 128B-aligned so
    // base + (chunk<<4) == base ^ (chunk<<4), and ((ks<<1)|lg)^key =
    // (ks<<1)^lg^key (disjoint bits).
    uint32_t bfold = (uint32_t)((lgB ^ (lrB & 7)) << 4);
    uint32_t afold = (uint32_t)(lgA << 4);
    uint32_t brow1_0 = (uint32_t)((n1_0 + lrB) << 7);
    uint32_t brow2_0 = (uint32_t)((n2_0 + lrB) << 7);

    int rB13[2]; uint32_t bOff[2];
#pragma unroll
    for (int mt = 0; mt < 2; mt++) {
        int m = m0 + mt * 16 + lrA;
        int bb = (m < 120) ? (m / 60) : 0;
        int r  = (m < 120) ? (m - bb * 60) : (m - 120);
        rB13[mt] = r * KW;
        bOff[mt] = (uint32_t)(bb * 7680);
    }

    float acc[2][8][4];
#pragma unroll
    for (int a = 0; a < 2; a++)
#pragma unroll
        for (int b = 0; b < 8; b++)
#pragma unroll
            for (int c = 0; c < 4; c++) acc[a][b][c] = 0.0f;

    const int S = 3 * KW;   // 39
    for (int sp = 0; sp < S; sp += 2) {
        CP_WAIT(0);          // W(sp), W(sp+1) resident
        __syncthreads();     // also: reads of slots (sp+2)%4,(sp+3)%4 done

        // prefetch W(sp+2), W(sp+3) into their slots (one group)
#pragma unroll
        for (int d = 2; d <= 3; d++) {
            int sn = sp + d;
            if (sn < S) {
                uint32_t slot = sbase + FWO + (uint32_t)(sn & 3) * 16384u;
                if (sn < KW) {
                    const char* ws = (const char*)g_W1p
                                   + ((size_t)(sn * CMID + wrow1) << 7) + (size_t)(wq1 * 32);
                    uint32_t dst = slot + (uint32_t)(wrow1 * 128 + wq1 * 32);
                    CP_ASYNC16(dst, ws); CP_ASYNC16(dst + 16, ws + 16);
                } else {
                    int k = sn - KW;
                    const __half* Wp = g_W2p;
                    if (k >= KW) { k -= KW; Wp = g_W3p; }
                    const char* ws = (const char*)Wp
                                   + ((size_t)(k * COUT + wrow2) << 7) + (size_t)(wh2 * 64);
                    uint32_t dst = slot + (uint32_t)(wrow2 * 128 + wh2 * 64);
#pragma unroll
                    for (int g = 0; g < 4; g++) CP_ASYNC16(dst + (g << 4), ws + (g << 4));
                }
            }
        }
        CP_COMMIT();

        // compute the two stages of this pair
#pragma unroll
        for (int d = 0; d < 2; d++) {
            int s = sp + d;
            if (s >= S) break;

            if (s == KW) {
                // conv1 -> y2 phase switch: all warps done reading y1 first
                __syncthreads();
#pragma unroll
                for (int mt = 0; mt < 2; mt++)
#pragma unroll
                    for (int nt = 0; nt < 4; nt++) {
                        float* dd = acc[mt][nt];
                        int o = n1_0 + nt * 8 + ((l & 3) << 1);
                        float cv0 = sb[o],       cv1 = sb[o + 1];
                        float i0  = sb[64 + o],  i1  = sb[65 + o];
                        float a0  = sb[128 + o], a1  = sb[129 + o];
#pragma unroll
                        for (int h = 0; h < 2; h++) {
                            int m = m0 + mt * 16 + (l >> 2) + h * 8;
                            if (m < 120) {
                                int r = (m >= 60) ? (m - 60) : m;
                                float y0 = fmaxf(fmaf(dd[h * 2]     + cv0, i0, a0), 0.0f);
                                float y1 = fmaxf(fmaf(dd[h * 2 + 1] + cv1, i1, a1), 0.0f);
                                uint32_t off = (uint32_t)(m * 128
                                             + (((o >> 3) ^ (r & 7)) << 4) + ((o & 7) << 1));
                                *(__half2*)(smb + FY12 + off) = __floats2half2_rn(y0, y1);
                            }
                        }
                    }
#pragma unroll
                for (int a = 0; a < 2; a++)
#pragma unroll
                    for (int b = 0; b < 8; b++)
#pragma unroll
                        for (int c = 0; c < 4; c++) acc[a][b][c] = 0.0f;
                __syncthreads();   // y2 visible before conv2 reads
            }

            uint32_t Wb = sbase + FWO + (uint32_t)(s & 3) * 16384u;

            if (s < KW) {
                uint32_t CA[2];
#pragma unroll
                for (int mt = 0; mt < 2; mt++) {
                    int j = snei[rB13[mt] + s];
                    CA[mt] = (sbase + FY12 + bOff[mt] + (uint32_t)(j << 7))
                           ^ afold ^ (uint32_t)((j & 7) << 4);
                }
                uint32_t CB0 = (Wb + brow1_0)         ^ bfold;
                uint32_t CB1 = (Wb + brow1_0 + 2048u) ^ bfold;
#pragma unroll
                for (int ks = 0; ks < 4; ks++) {
                    uint32_t kx = (uint32_t)(ks << 5);
                    uint32_t af[2][4];
                    LDMX4(af[0][0], af[0][1], af[0][2], af[0][3], CA[0] ^ kx);
                    LDMX4(af[1][0], af[1][1], af[1][2], af[1][3], CA[1] ^ kx);
                    {
                        uint32_t bh[4];
                        LDMX4(bh[0], bh[1], bh[2], bh[3], CB0 ^ kx);
#pragma unroll
                        for (int mt = 0; mt < 2; mt++)
#pragma unroll
                            for (int hf = 0; hf < 2; hf++)
                                mma_f16(acc[mt][hf], af[mt], &bh[hf * 2]);
                    }
                    {
                        uint32_t bh[4];
                        LDMX4(bh[0], bh[1], bh[2], bh[3], CB1 ^ kx);
#pragma unroll
                        for (int mt = 0; mt < 2; mt++)
#pragma unroll
                            for (int hf = 0; hf < 2; hf++)
                                mma_f16(acc[mt][2 + hf], af[mt], &bh[hf * 2]);
                    }
                }
            } else {
                int ph = (s >= 2 * KW);
                int kk = s - (ph ? 2 * KW : KW);
                uint32_t Yb = sbase + (ph ? FY3 : FY12);
                uint32_t CA[2];
#pragma unroll
                for (int mt = 0; mt < 2; mt++) {
                    int j = snei[rB13[mt] + kk];
                    CA[mt] = (Yb + bOff[mt] + (uint32_t)(j << 7))
                           ^ afold ^ (uint32_t)((j & 7) << 4);
                }
                uint32_t CB[4];
#pragma unroll
                for (int q = 0; q < 4; q++)
                    CB[q] = (Wb + brow2_0 + (uint32_t)(q * 2048)) ^ bfold;
#pragma unroll
                for (int ks = 0; ks < 4; ks++) {
                    uint32_t kx = (uint32_t)(ks << 5);
                    uint32_t af[2][4];
                    LDMX4(af[0][0], af[0][1], af[0][2], af[0][3], CA[0] ^ kx);
                    LDMX4(af[1][0], af[1][1], af[1][2], af[1][3], CA[1] ^ kx);
#pragma unroll
                    for (int q = 0; q < 4; q++) {
                        uint32_t bh[4];
                        LDMX4(bh[0], bh[1], bh[2], bh[3], CB[q] ^ kx);
#pragma unroll
                        for (int mt = 0; mt < 2; mt++)
#pragma unroll
                            for (int hf = 0; hf < 2; hf++)
                                mma_f16(acc[mt][q * 2 + hf], af[mt], &bh[hf * 2]);
                    }
                }
            }
        }
    }

    // final epilogue: +(c2+c3), out [b][o][r]
#pragma unroll
    for (int mt = 0; mt < 2; mt++)
#pragma unroll
        for (int nc = 0; nc < 8; nc++) {
            float* d = acc[mt][nc];
            int o = n2_0 + nc * 8 + ((l & 3) << 1);
            float bv0 = sb[448 + o], bv1 = sb[449 + o];
#pragma unroll
            for (int h = 0; h < 2; h++) {
                int m = m0 + mt * 16 + (l >> 2) + h * 8;
                if (m < 120) {
                    int bb = m / 60; int r = m - bb * 60;
                    float* dp = out + ((size_t)(b0 + bb) * COUT + o) * RPOS + r;
                    dp[0]    = d[h * 2]     + bv0;
                    dp[RPOS] = d[h * 2 + 1] + bv1;
                }
            }
        }
}

extern "C" void kernel_launch(void* const* d_in, const int* in_sizes, int n_in,
                              void* d_out, int out_size)
{
    const float* x   = (const float*)d_in[0];
    const int*   nei = (const int*)d_in[1];
    const float* g1 = (const float*)d_in[2];
    const float* b1 = (const float*)d_in[3];
    const float* m1 = (const float*)d_in[4];
    const float* v1 = (const float*)d_in[5];
    const float* W1 = (const float*)d_in[6];
    const float* c1 = (const float*)d_in[7];
    const float* g2 = (const float*)d_in[8];
    const float* b2 = (const float*)d_in[9];
    const float* m2 = (const float*)d_in[10];
    const float* v2 = (const float*)d_in[11];
    const float* W2 = (const float*)d_in[12];
    const float* c2 = (const float*)d_in[13];
    const float* g3 = (const float*)d_in[14];
    const float* b3 = (const float*)d_in[15];
    const float* m3 = (const float*)d_in[16];
    const float* v3 = (const float*)d_in[17];
    const float* W3 = (const float*)d_in[18];
    const float* c3 = (const float*)d_in[19];
    float* out = (float*)d_out;

    const int smem_fused = (int)FTOT + 256;
    cudaFuncSetAttribute(fused_kernel, cudaFuncAttributeMaxDynamicSharedMemorySize, smem_fused);

    packW_kernel<<<(KW * (CMID * CIN + 2 * COUT * CMID) + 255) / 256, 256>>>(W1, W2, W3);
    fused_kernel<<<BATCH / 2, 256, smem_fused>>>(x, nei,
        g1, b1, m1, v1, c1, g2, b2, m2, v2, g3, b3, m3, v3, c2, c3, out);
}

// round 17
// speedup vs baseline: 1.0015x; 1.0015x over previous
#include <cuda_runtime.h>
#include <cuda_fp16.h>
#include <cstdint>

#define BATCH 2048
#define RPOS  60
#define KW    13
#define CIN   64
#define CMID  64
#define COUT  128
#define EPSV  1e-5f

__device__ __align__(128) __half g_W1p[KW * CMID * CIN];
__device__ __align__(128) __half g_W2p[KW * COUT * CMID];
__device__ __align__(128) __half g_W3p[KW * COUT * CMID];

__device__ __forceinline__ uint32_t smem_u32(const void* p) {
    uint32_t a;
    asm("{ .reg .u64 t; cvta.to.shared.u64 t, %1; cvt.u32.u64 %0, t; }" : "=r"(a) : "l"(p));
    return a;
}

#define CP_ASYNC16(dst, src) \
    asm volatile("cp.async.cg.shared.global [%0], [%1], 16;" :: "r"(dst), "l"(src) : "memory")
#define CP_COMMIT()  asm volatile("cp.async.commit_group;" ::: "memory")
#define CP_WAIT(n)   asm volatile("cp.async.wait_group %0;" :: "n"(n) : "memory")

#define LDMX4(r0, r1, r2, r3, addr) \
    asm volatile("ldmatrix.sync.aligned.m8n8.x4.shared.b16 {%0,%1,%2,%3}, [%4];" \
        : "=r"(r0), "=r"(r1), "=r"(r2), "=r"(r3) : "r"(addr))

__device__ __forceinline__ void mma_f16(float* d, const uint32_t* a, const uint32_t* b) {
    asm volatile("mma.sync.aligned.m16n8k16.row.col.f32.f16.f16.f32 "
        "{%0,%1,%2,%3},{%4,%5,%6,%7},{%8,%9},{%0,%1,%2,%3};"
        : "+f"(d[0]), "+f"(d[1]), "+f"(d[2]), "+f"(d[3])
        : "r"(a[0]), "r"(a[1]), "r"(a[2]), "r"(a[3]), "r"(b[0]), "r"(b[1]));
}

__global__ void packW_kernel(const float* __restrict__ W1, const float* __restrict__ W2,
                             const float* __restrict__ W3)
{
    int idx = blockIdx.x * 256 + threadIdx.x;
    const int n1 = KW * CMID * CIN, n2 = KW * COUT * CMID;
    const float* W; __half* dst; int O, nloc;
    if (idx < n1)              { W = W1; dst = g_W1p; O = CMID; nloc = idx;           }
    else if (idx < n1 + n2)    { W = W2; dst = g_W2p; O = COUT; nloc = idx - n1;      }
    else if (idx < n1 + 2*n2)  { W = W3; dst = g_W3p; O = COUT; nloc = idx - n1 - n2; }
    else return;
    int k = nloc / (O * 64), rem = nloc % (O * 64);
    int o = rem / 64, c = rem % 64;
    float v = W[o * (64 * KW) + c * KW + k];
    int sw = ((c >> 3) ^ (o & 7)) * 8 + (c & 7);
    dst[(size_t)(k * O + o) * 64 + sw] = __float2half_rn(v);
}

// smem (per CTA, ~99.4 KB -> 2 CTAs/SM at 128 regs):
//   FY12: y1 during conv1, overwritten by y2 at phase switch (15360)
//   FY3 : y3 (15360)
//   FWO : W QUAD buffer 4x16384 (x staging overlaps in prologue)
#define FY12  0u
#define FY3   15360u
#define FWO   30720u
#define FNEI  96256u
#define FBIAS (FNEI + 3200u)
#define FTOT  (FBIAS + 2304u)

__global__ __launch_bounds__(256, 2)
void fused_kernel(const float* __restrict__ x, const int* __restrict__ nei,
                  const float* __restrict__ g1, const float* __restrict__ b1,
                  const float* __restrict__ m1, const float* __restrict__ v1,
                  const float* __restrict__ c1,
                  const float* __restrict__ g2, const float* __restrict__ b2,
                  const float* __restrict__ m2, const float* __restrict__ v2,
                  const float* __restrict__ g3, const float* __restrict__ b3,
                  const float* __restrict__ m3, const float* __restrict__ v3,
                  const float* __restrict__ cc2, const float* __restrict__ cc3,
                  float* __restrict__ out)
{
    extern __shared__ __align__(1024) char smb[];
    uint32_t sbase = smem_u32(smb);

    int t = threadIdx.x, wid = t >> 5, l = t & 31;
    int*   snei = (int*)(smb + FNEI);
    float* sb   = (float*)(smb + FBIAS);

    for (int i = t; i < RPOS * KW; i += 256) snei[i] = nei[i];
    if (t < 64) {
        sb[t] = c1[t];
        float iv = g2[t] * rsqrtf(v2[t] + EPSV);
        sb[64 + t] = iv; sb[128 + t] = b2[t] - m2[t] * iv;
        float i1 = g1[t] * rsqrtf(v1[t] + EPSV);
        sb[192 + t] = i1; sb[256 + t] = b1[t] - m1[t] * i1;
        float i3 = g3[t] * rsqrtf(v3[t] + EPSV);
        sb[320 + t] = i3; sb[384 + t] = b3[t] - m3[t] * i3;
    }
    if (t < 128) sb[448 + t] = cc2[t] + cc3[t];

    int b0 = blockIdx.x * 2;

    // prologue A: stage x into W-buffer region (floats, [bb][c][j] stride 61)
    float* xs = (float*)(smb + FWO);
    const float* xsrc = x + (size_t)b0 * (CIN * RPOS);
    for (int i = t; i < 2 * CIN * RPOS; i += 256) {
        int bb = i / 3840, rem = i - bb * 3840;
        int c = rem / 60, j = rem - c * 60;
        xs[(bb * 64 + c) * 61 + j] = xsrc[i];
    }
    __syncthreads();

    // prologue B: y1 (-> FY12), y3 fp16 tiles; per-row swizzle key = r&7
    for (int i = t; i < 2 * RPOS * 32; i += 256) {
        int bb = i / 1920, rem = i - bb * 1920;
        int r = rem >> 5, cp = rem & 31, c = cp * 2;
        const float* xc = xs + (bb * 64 + c) * 61 + r;
        float xa = xc[0], xb2 = xc[61];
        float a1  = fmaxf(fmaf(xa,  sb[192 + c], sb[256 + c]), 0.0f);
        float b1v = fmaxf(fmaf(xb2, sb[193 + c], sb[257 + c]), 0.0f);
        float a3  = fmaxf(fmaf(xa,  sb[320 + c], sb[384 + c]), 0.0f);
        float b3v = fmaxf(fmaf(xb2, sb[321 + c], sb[385 + c]), 0.0f);
        uint32_t off = (uint32_t)((bb * 60 + r) * 128
                     + (((cp >> 2) ^ (r & 7)) << 4) + ((cp & 3) << 2));
        *(__half2*)(smb + FY12 + off) = __floats2half2_rn(a1, b1v);
        *(__half2*)(smb + FY3  + off) = __floats2half2_rn(a3, b3v);
    }
    __syncthreads();   // xs consumed; W prefetch may overwrite

    int wrow1 = t >> 2, wq1 = t & 3;   // conv1 W: 64 rows x 32B
    int wrow2 = t >> 1, wh2 = t & 1;   // conv2 W: 128 rows x 64B

    // W prefetch helper (stage index sn; no-op if sn >= S)
    auto prefetchW = [&](int sn) {
        if (sn >= 3 * KW) return;
        uint32_t slot = sbase + FWO + (uint32_t)(sn & 3) * 16384u;
        if (sn < KW) {
            const char* ws = (const char*)g_W1p
                           + ((size_t)(sn * CMID + wrow1) << 7) + (size_t)(wq1 * 32);
            uint32_t dst = slot + (uint32_t)(wrow1 * 128 + wq1 * 32);
            CP_ASYNC16(dst, ws); CP_ASYNC16(dst + 16, ws + 16);
        } else {
            int k = sn - KW;
            const __half* Wp = g_W2p;
            if (k >= KW) { k -= KW; Wp = g_W3p; }
            const char* ws = (const char*)Wp
                           + ((size_t)(k * COUT + wrow2) << 7) + (size_t)(wh2 * 64);
            uint32_t dst = slot + (uint32_t)(wrow2 * 128 + wh2 * 64);
#pragma unroll
            for (int g = 0; g < 4; g++) CP_ASYNC16(dst + (g << 4), ws + (g << 4));
        }
    };

    // prefetch stages 0,1 into slots 0,1 (one group)
    prefetchW(0); prefetchW(1); CP_COMMIT();

    int m0 = (wid & 3) * 32;
    int n1_0 = (wid >> 2) * 32;
    int n2_0 = (wid >> 2) * 64;
    int lrA = l & 15, lgA = l >> 4;
    int lrB = (l & 7) + ((l >> 4) << 3), lgB = (l >> 3) & 1;
    uint32_t bfold = (uint32_t)((lgB ^ (lrB & 7)) << 4);
    uint32_t afold = (uint32_t)(lgA << 4);
    uint32_t brow1_0 = (uint32_t)((n1_0 + lrB) << 7);
    uint32_t brow2_0 = (uint32_t)((n2_0 + lrB) << 7);

    int rB13[2]; uint32_t bOff[2];
#pragma unroll
    for (int mt = 0; mt < 2; mt++) {
        int m = m0 + mt * 16 + lrA;
        int bb = (m < 120) ? (m / 60) : 0;
        int r  = (m < 120) ? (m - bb * 60) : (m - 120);
        rB13[mt] = r * KW;
        bOff[mt] = (uint32_t)(bb * 7680);
    }

    float acc[2][8][4];
#pragma unroll
    for (int a = 0; a < 2; a++)
#pragma unroll
        for (int b = 0; b < 8; b++)
#pragma unroll
            for (int c = 0; c < 4; c++) acc[a][b][c] = 0.0f;

    // conv1 compute for stage s (W slot = s&3), reads y1 at FY12
    auto conv1_stage = [&](int s) {
        uint32_t Wb = sbase + FWO + (uint32_t)(s & 3) * 16384u;
        uint32_t CA[2];
#pragma unroll
        for (int mt = 0; mt < 2; mt++) {
            int j = snei[rB13[mt] + s];
            CA[mt] = (sbase + FY12 + bOff[mt] + (uint32_t)(j << 7))
                   ^ afold ^ (uint32_t)((j & 7) << 4);
        }
        uint32_t CB0 = (Wb + brow1_0)         ^ bfold;
        uint32_t CB1 = (Wb + brow1_0 + 2048u) ^ bfold;
#pragma unroll
        for (int ks = 0; ks < 4; ks++) {
            uint32_t kx = (uint32_t)(ks << 5);
            uint32_t af[2][4];
            LDMX4(af[0][0], af[0][1], af[0][2], af[0][3], CA[0] ^ kx);
            LDMX4(af[1][0], af[1][1], af[1][2], af[1][3], CA[1] ^ kx);
            {
                uint32_t bh[4];
                LDMX4(bh[0], bh[1], bh[2], bh[3], CB0 ^ kx);
#pragma unroll
                for (int mt = 0; mt < 2; mt++)
#pragma unroll
                    for (int hf = 0; hf < 2; hf++)
                        mma_f16(acc[mt][hf], af[mt], &bh[hf * 2]);
            }
            {
                uint32_t bh[4];
                LDMX4(bh[0], bh[1], bh[2], bh[3], CB1 ^ kx);
#pragma unroll
                for (int mt = 0; mt < 2; mt++)
#pragma unroll
                    for (int hf = 0; hf < 2; hf++)
                        mma_f16(acc[mt][2 + hf], af[mt], &bh[hf * 2]);
            }
        }
    };

    // conv2 compute for stage s, k-index kk, y tile at ybase
    auto conv2_stage = [&](int s, int kk, uint32_t ybase) {
        uint32_t Wb = sbase + FWO + (uint32_t)(s & 3) * 16384u;
        uint32_t CA[2];
#pragma unroll
        for (int mt = 0; mt < 2; mt++) {
            int j = snei[rB13[mt] + kk];
            CA[mt] = (sbase + ybase + bOff[mt] + (uint32_t)(j << 7))
                   ^ afold ^ (uint32_t)((j & 7) << 4);
        }
        uint32_t CB[4];
#pragma unroll
        for (int q = 0; q < 4; q++)
            CB[q] = (Wb + brow2_0 + (uint32_t)(q * 2048)) ^ bfold;
#pragma unroll
        for (int ks = 0; ks < 4; ks++) {
            uint32_t kx = (uint32_t)(ks << 5);
            uint32_t af[2][4];
            LDMX4(af[0][0], af[0][1], af[0][2], af[0][3], CA[0] ^ kx);
            LDMX4(af[1][0], af[1][1], af[1][2], af[1][3], CA[1] ^ kx);
#pragma unroll
            for (int q = 0; q < 4; q++) {
                uint32_t bh[4];
                LDMX4(bh[0], bh[1], bh[2], bh[3], CB[q] ^ kx);
#pragma unroll
                for (int mt = 0; mt < 2; mt++)
#pragma unroll
                    for (int hf = 0; hf < 2; hf++)
                        mma_f16(acc[mt][q * 2 + hf], af[mt], &bh[hf * 2]);
            }
        }
    };

    // ---- phase 1: conv1 stages 0..11 (6 pairs) ----
    for (int sp = 0; sp < 12; sp += 2) {
        CP_WAIT(0);
        __syncthreads();
        prefetchW(sp + 2); prefetchW(sp + 3); CP_COMMIT();
        conv1_stage(sp);
        conv1_stage(sp + 1);
    }

    // ---- boundary pair: stage 12 (conv1 last) + phase switch + stage 13 ----
    CP_WAIT(0);
    __syncthreads();
    prefetchW(14); prefetchW(15); CP_COMMIT();
    conv1_stage(12);

    __syncthreads();   // all warps done reading y1
#pragma unroll
    for (int mt = 0; mt < 2; mt++)
#pragma unroll
        for (int nt = 0; nt < 4; nt++) {
            float* dd = acc[mt][nt];
            int o = n1_0 + nt * 8 + ((l & 3) << 1);
            float cv0 = sb[o],       cv1 = sb[o + 1];
            float i0  = sb[64 + o],  i1  = sb[65 + o];
            float a0  = sb[128 + o], a1  = sb[129 + o];
#pragma unroll
            for (int h = 0; h < 2; h++) {
                int m = m0 + mt * 16 + (l >> 2) + h * 8;
                if (m < 120) {
                    int r = (m >= 60) ? (m - 60) : m;
                    float y0 = fmaxf(fmaf(dd[h * 2]     + cv0, i0, a0), 0.0f);
                    float y1 = fmaxf(fmaf(dd[h * 2 + 1] + cv1, i1, a1), 0.0f);
                    uint32_t off = (uint32_t)(m * 128
                                 + (((o >> 3) ^ (r & 7)) << 4) + ((o & 7) << 1));
                    *(__half2*)(smb + FY12 + off) = __floats2half2_rn(y0, y1);
                }
            }
        }
#pragma unroll
    for (int a = 0; a < 2; a++)
#pragma unroll
        for (int b = 0; b < 8; b++)
#pragma unroll
            for (int c = 0; c < 4; c++) acc[a][b][c] = 0.0f;
    __syncthreads();   // y2 visible

    conv2_stage(13, 0, FY12);

    // ---- phase 2: conv2 on y2, stages 14..25 (6 pairs) ----
    for (int sp = 14; sp < 26; sp += 2) {
        CP_WAIT(0);
        __syncthreads();
        prefetchW(sp + 2); prefetchW(sp + 3); CP_COMMIT();
        conv2_stage(sp,     sp - 13, FY12);
        conv2_stage(sp + 1, sp - 12, FY12);
    }

    // ---- phase 3: conv2 on y3, stages 26..37 (6 pairs) ----
    for (int sp = 26; sp < 38; sp += 2) {
        CP_WAIT(0);
        __syncthreads();
        prefetchW(sp + 2); prefetchW(sp + 3); CP_COMMIT();
        conv2_stage(sp,     sp - 26, FY3);
        conv2_stage(sp + 1, sp - 25, FY3);
    }

    // ---- final stage 38 ----
    CP_WAIT(0);
    __syncthreads();
    conv2_stage(38, 12, FY3);

    // final epilogue: +(c2+c3), out [b][o][r]
#pragma unroll
    for (int mt = 0; mt < 2; mt++)
#pragma unroll
        for (int nc = 0; nc < 8; nc++) {
            float* d = acc[mt][nc];
            int o = n2_0 + nc * 8 + ((l & 3) << 1);
            float bv0 = sb[448 + o], bv1 = sb[449 + o];
#pragma unroll
            for (int h = 0; h < 2; h++) {
                int m = m0 + mt * 16 + (l >> 2) + h * 8;
                if (m < 120) {
                    int bb = m / 60; int r = m - bb * 60;
                    float* dp = out + ((size_t)(b0 + bb) * COUT + o) * RPOS + r;
                    dp[0]    = d[h * 2]     + bv0;
                    dp[RPOS] = d[h * 2 + 1] + bv1;
                }
            }
        }
}

extern "C" void kernel_launch(void* const* d_in, const int* in_sizes, int n_in,
                              void* d_out, int out_size)
{
    const float* x   = (const float*)d_in[0];
    const int*   nei = (const int*)d_in[1];
    const float* g1 = (const float*)d_in[2];
    const float* b1 = (const float*)d_in[3];
    const float* m1 = (const float*)d_in[4];
    const float* v1 = (const float*)d_in[5];
    const float* W1 = (const float*)d_in[6];
    const float* c1 = (const float*)d_in[7];
    const float* g2 = (const float*)d_in[8];
    const float* b2 = (const float*)d_in[9];
    const float* m2 = (const float*)d_in[10];
    const float* v2 = (const float*)d_in[11];
    const float* W2 = (const float*)d_in[12];
    const float* c2 = (const float*)d_in[13];
    const float* g3 = (const float*)d_in[14];
    const float* b3 = (const float*)d_in[15];
    const float* m3 = (const float*)d_in[16];
    const float* v3 = (const float*)d_in[17];
    const float* W3 = (const float*)d_in[18];
    const float* c3 = (const float*)d_in[19];
    float* out = (float*)d_out;

    const int smem_fused = (int)FTOT + 256;
    cudaFuncSetAttribute(fused_kernel, cudaFuncAttributeMaxDynamicSharedMemorySize, smem_fused);

    packW_kernel<<<(KW * (CMID * CIN + 2 * COUT * CMID) + 255) / 256, 256>>>(W1, W2, W3);
    fused_kernel<<<BATCH / 2, 256, smem_fused>>>(x, nei,
        g1, b1, m1, v1, c1, g2, b2, m2, v2, g3, b3, m3, v3, c2, c3, out);
}